// round 1
// baseline (speedup 1.0000x reference)
#include <cuda_runtime.h>

#define NE 8        // experts
#define DD 512      // model dim
#define HH 2048     // hidden dim
#define NTOK 4096   // tokens (2*2048)
#define CAP 4096    // worst-case tokens per expert

// ---- device scratch (allocation-free: static globals) ----
__device__ int   g_cnt[NE];
__device__ int   g_tok[NE * CAP];
__device__ float g_w[NE * CAP];
__device__ float g_h[(size_t)NE * CAP * HH];   // 256 MB hidden activations

// ============================================================================
// Gate: logits -> softmax -> top-2 -> routing lists + gate_weights output
// one warp per token
// ============================================================================
__global__ void gate_kernel(const float* __restrict__ x,
                            const float* __restrict__ Wg,
                            const float* __restrict__ bg,
                            float* __restrict__ gates_out) {
    __shared__ float sWg[DD * NE];   // 16 KB
    for (int i = threadIdx.x; i < DD * NE; i += blockDim.x) sWg[i] = Wg[i];
    __syncthreads();

    const int warp = threadIdx.x >> 5;
    const int lane = threadIdx.x & 31;
    const int t = blockIdx.x * (blockDim.x >> 5) + warp;
    if (t >= NTOK) return;

    float acc[NE];
#pragma unroll
    for (int e = 0; e < NE; e++) acc[e] = 0.f;

    const float* xr = x + (size_t)t * DD;
    for (int d = lane; d < DD; d += 32) {
        float xv = xr[d];
#pragma unroll
        for (int e = 0; e < NE; e++) acc[e] = fmaf(xv, sWg[d * NE + e], acc[e]);
    }
#pragma unroll
    for (int off = 16; off; off >>= 1) {
#pragma unroll
        for (int e = 0; e < NE; e++)
            acc[e] += __shfl_xor_sync(0xffffffffu, acc[e], off);
    }

    if (lane == 0) {
        float lg[NE];
        float m = -1e30f;
#pragma unroll
        for (int e = 0; e < NE; e++) { lg[e] = acc[e] + bg[e]; m = fmaxf(m, lg[e]); }
        float s = 0.f;
#pragma unroll
        for (int e = 0; e < NE; e++) { lg[e] = expf(lg[e] - m); s += lg[e]; }
        float inv = 1.f / s;
#pragma unroll
        for (int e = 0; e < NE; e++) lg[e] *= inv;

        if (gates_out) {
#pragma unroll
            for (int e = 0; e < NE; e++) gates_out[(size_t)t * NE + e] = lg[e];
        }

        // top-2 (first index wins ties, matching jax.lax.top_k)
        int i1 = 0; float v1 = lg[0];
#pragma unroll
        for (int e = 1; e < NE; e++) if (lg[e] > v1) { v1 = lg[e]; i1 = e; }
        int i2 = -1; float v2 = -1.f;
#pragma unroll
        for (int e = 0; e < NE; e++) if (e != i1 && lg[e] > v2) { v2 = lg[e]; i2 = e; }

        int p1 = atomicAdd(&g_cnt[i1], 1);
        g_tok[i1 * CAP + p1] = t; g_w[i1 * CAP + p1] = v1;
        int p2 = atomicAdd(&g_cnt[i2], 1);
        g_tok[i2 * CAP + p2] = t; g_w[i2 * CAP + p2] = v2;
    }
}

// ============================================================================
// FC1: h = relu(gather(X) @ W1[e] + b1[e])   [cnt x 512] @ [512 x 2048]
// 64x64 tile, BK=16, 256 threads, 4x4 per-thread microtile
// ============================================================================
__global__ void expert_fc1(const float* __restrict__ x,
                           const float* __restrict__ W1,
                           const float* __restrict__ b1) {
    const int e = blockIdx.z;
    const int cnt = g_cnt[e];
    const int m0 = blockIdx.x * 64;
    if (m0 >= cnt) return;
    const int n0 = blockIdx.y * 64;

    __shared__ float As[16][68];   // A transposed [k][m], padded
    __shared__ float Bs[16][64];
    __shared__ int   stok[64];

    const int tid = threadIdx.x;
    if (tid < 64) {
        int r = m0 + tid;
        stok[tid] = (r < cnt) ? g_tok[e * CAP + r] : g_tok[e * CAP + m0];
    }
    __syncthreads();

    const float* B = W1 + (size_t)e * DD * HH;
    const int am = tid >> 2, akq = tid & 3;     // A load: row am, float4 quad akq
    const int bk = tid >> 4, bnq = tid & 15;    // B load: k-row bk, quad bnq
    const int ty = tid >> 4, tx = tid & 15;     // compute mapping

    float c[4][4];
#pragma unroll
    for (int i = 0; i < 4; i++)
#pragma unroll
        for (int j = 0; j < 4; j++) c[i][j] = 0.f;

    const float* arow = x + (size_t)stok[am] * DD;

    for (int k0 = 0; k0 < DD; k0 += 16) {
        float4 av = *(const float4*)(arow + k0 + akq * 4);
        As[akq * 4 + 0][am] = av.x;
        As[akq * 4 + 1][am] = av.y;
        As[akq * 4 + 2][am] = av.z;
        As[akq * 4 + 3][am] = av.w;
        float4 bv = *(const float4*)(B + (size_t)(k0 + bk) * HH + n0 + bnq * 4);
        *(float4*)&Bs[bk][bnq * 4] = bv;
        __syncthreads();
#pragma unroll
        for (int k = 0; k < 16; k++) {
            float4 a = *(const float4*)&As[k][ty * 4];
            float4 b = *(const float4*)&Bs[k][tx * 4];
            c[0][0] = fmaf(a.x, b.x, c[0][0]); c[0][1] = fmaf(a.x, b.y, c[0][1]);
            c[0][2] = fmaf(a.x, b.z, c[0][2]); c[0][3] = fmaf(a.x, b.w, c[0][3]);
            c[1][0] = fmaf(a.y, b.x, c[1][0]); c[1][1] = fmaf(a.y, b.y, c[1][1]);
            c[1][2] = fmaf(a.y, b.z, c[1][2]); c[1][3] = fmaf(a.y, b.w, c[1][3]);
            c[2][0] = fmaf(a.z, b.x, c[2][0]); c[2][1] = fmaf(a.z, b.y, c[2][1]);
            c[2][2] = fmaf(a.z, b.z, c[2][2]); c[2][3] = fmaf(a.z, b.w, c[2][3]);
            c[3][0] = fmaf(a.w, b.x, c[3][0]); c[3][1] = fmaf(a.w, b.y, c[3][1]);
            c[3][2] = fmaf(a.w, b.z, c[3][2]); c[3][3] = fmaf(a.w, b.w, c[3][3]);
        }
        __syncthreads();
    }

    float4 bias = *(const float4*)(b1 + (size_t)e * HH + n0 + tx * 4);
#pragma unroll
    for (int i = 0; i < 4; i++) {
        int row = m0 + ty * 4 + i;
        if (row < cnt) {
            float4 v;
            v.x = fmaxf(c[i][0] + bias.x, 0.f);
            v.y = fmaxf(c[i][1] + bias.y, 0.f);
            v.z = fmaxf(c[i][2] + bias.z, 0.f);
            v.w = fmaxf(c[i][3] + bias.w, 0.f);
            *(float4*)&g_h[((size_t)e * CAP + row) * HH + n0 + tx * 4] = v;
        }
    }
}

// ============================================================================
// FC2: y = h @ W2[e] + b2[e]; out[tok] += combine * y  (atomic scatter)
// [cnt x 2048] @ [2048 x 512]
// ============================================================================
__global__ void expert_fc2(const float* __restrict__ W2,
                           const float* __restrict__ b2,
                           float* __restrict__ out) {
    const int e = blockIdx.z;
    const int cnt = g_cnt[e];
    const int m0 = blockIdx.x * 64;
    if (m0 >= cnt) return;
    const int n0 = blockIdx.y * 64;

    __shared__ float As[16][68];
    __shared__ float Bs[16][64];

    const int tid = threadIdx.x;
    const float* A = g_h + (size_t)e * CAP * HH;
    const float* B = W2 + (size_t)e * HH * DD;
    const int am = tid >> 2, akq = tid & 3;
    const int bk = tid >> 4, bnq = tid & 15;
    const int ty = tid >> 4, tx = tid & 15;

    float c[4][4];
#pragma unroll
    for (int i = 0; i < 4; i++)
#pragma unroll
        for (int j = 0; j < 4; j++) c[i][j] = 0.f;

    int arow_idx = m0 + am; if (arow_idx >= cnt) arow_idx = m0;
    const float* arow = A + (size_t)arow_idx * HH;

    for (int k0 = 0; k0 < HH; k0 += 16) {
        float4 av = *(const float4*)(arow + k0 + akq * 4);
        As[akq * 4 + 0][am] = av.x;
        As[akq * 4 + 1][am] = av.y;
        As[akq * 4 + 2][am] = av.z;
        As[akq * 4 + 3][am] = av.w;
        float4 bv = *(const float4*)(B + (size_t)(k0 + bk) * DD + n0 + bnq * 4);
        *(float4*)&Bs[bk][bnq * 4] = bv;
        __syncthreads();
#pragma unroll
        for (int k = 0; k < 16; k++) {
            float4 a = *(const float4*)&As[k][ty * 4];
            float4 b = *(const float4*)&Bs[k][tx * 4];
            c[0][0] = fmaf(a.x, b.x, c[0][0]); c[0][1] = fmaf(a.x, b.y, c[0][1]);
            c[0][2] = fmaf(a.x, b.z, c[0][2]); c[0][3] = fmaf(a.x, b.w, c[0][3]);
            c[1][0] = fmaf(a.y, b.x, c[1][0]); c[1][1] = fmaf(a.y, b.y, c[1][1]);
            c[1][2] = fmaf(a.y, b.z, c[1][2]); c[1][3] = fmaf(a.y, b.w, c[1][3]);
            c[2][0] = fmaf(a.z, b.x, c[2][0]); c[2][1] = fmaf(a.z, b.y, c[2][1]);
            c[2][2] = fmaf(a.z, b.z, c[2][2]); c[2][3] = fmaf(a.z, b.w, c[2][3]);
            c[3][0] = fmaf(a.w, b.x, c[3][0]); c[3][1] = fmaf(a.w, b.y, c[3][1]);
            c[3][2] = fmaf(a.w, b.z, c[3][2]); c[3][3] = fmaf(a.w, b.w, c[3][3]);
        }
        __syncthreads();
    }

    float4 bias = *(const float4*)(b2 + (size_t)e * DD + n0 + tx * 4);
#pragma unroll
    for (int i = 0; i < 4; i++) {
        int row = m0 + ty * 4 + i;
        if (row < cnt) {
            int tok = g_tok[e * CAP + row];
            float w = g_w[e * CAP + row];
            float* orow = out + (size_t)tok * DD + n0 + tx * 4;
            atomicAdd(&orow[0], w * (c[i][0] + bias.x));
            atomicAdd(&orow[1], w * (c[i][1] + bias.y));
            atomicAdd(&orow[2], w * (c[i][2] + bias.z));
            atomicAdd(&orow[3], w * (c[i][3] + bias.w));
        }
    }
}

// ============================================================================
// launch
// ============================================================================
extern "C" void kernel_launch(void* const* d_in, const int* in_sizes, int n_in,
                              void* d_out, int out_size) {
    const float* x  = (const float*)d_in[0];
    const float* Wg = (const float*)d_in[1];
    const float* bg = (const float*)d_in[2];
    const float* W1 = (const float*)d_in[3];
    const float* b1 = (const float*)d_in[4];
    const float* W2 = (const float*)d_in[5];
    const float* b2 = (const float*)d_in[6];
    float* out = (float*)d_out;

    void* cntp = nullptr;
    cudaGetSymbolAddress(&cntp, g_cnt);

    cudaMemsetAsync(out, 0, (size_t)out_size * sizeof(float));
    cudaMemsetAsync(cntp, 0, NE * sizeof(int));

    // gate_weights are appended after out if the buffer includes them
    float* gates_out = nullptr;
    if ((size_t)out_size >= (size_t)NTOK * DD + (size_t)NTOK * NE)
        gates_out = out + (size_t)NTOK * DD;

    gate_kernel<<<NTOK / 8, 256>>>(x, Wg, bg, gates_out);
    expert_fc1<<<dim3(CAP / 64, HH / 64, NE), 256>>>(x, W1, b1);
    expert_fc2<<<dim3(CAP / 64, DD / 64, NE), 256>>>(W2, b2, out);
}

// round 3
// speedup vs baseline: 2.1621x; 2.1621x over previous
#include <cuda_runtime.h>
#include <cuda_bf16.h>
#include <cstdint>

#define NE 8
#define DD 512
#define HH 2048
#define NTOK 4096
#define CAP 4096

// ---------------- device scratch (static, allocation-free) ----------------
__device__ int   g_cnt[NE];
__device__ int   g_tok[NE * CAP];
__device__ float g_w[NE * CAP];
__device__ int   g_slot[NTOK * 2];
__device__ __nv_bfloat16 g_x_hi[(size_t)NTOK * DD];
__device__ __nv_bfloat16 g_x_lo[(size_t)NTOK * DD];
__device__ __nv_bfloat16 g_h_hi[(size_t)NE * CAP * HH];
__device__ __nv_bfloat16 g_h_lo[(size_t)NE * CAP * HH];
__device__ __nv_bfloat16 g_w1t_hi[(size_t)NE * HH * DD];   // [e][n(H)][k(D)]
__device__ __nv_bfloat16 g_w1t_lo[(size_t)NE * HH * DD];
__device__ __nv_bfloat16 g_w2t_hi[(size_t)NE * DD * HH];   // [e][n(D)][k(H)]
__device__ __nv_bfloat16 g_w2t_lo[(size_t)NE * DD * HH];
__device__ float g_y[(size_t)NE * CAP * DD];

// ---------------- helpers ----------------
__device__ __forceinline__ uint32_t smem_u32(const void* p) {
    uint32_t a;
    asm("{ .reg .u64 t; cvta.to.shared.u64 t, %1; cvt.u32.u64 %0, t; }" : "=r"(a) : "l"(p));
    return a;
}
#define CP_ASYNC16(dst, src) \
    asm volatile("cp.async.cg.shared.global [%0], [%1], 16;" :: "r"(dst), "l"(src) : "memory")
#define CP_COMMIT() asm volatile("cp.async.commit_group;" ::: "memory")
#define CP_WAIT(n)  asm volatile("cp.async.wait_group %0;" :: "n"(n) : "memory")

__device__ __forceinline__ void ldsm4(uint32_t* r, uint32_t addr) {
    asm volatile("ldmatrix.sync.aligned.m8n8.x4.shared.b16 {%0,%1,%2,%3}, [%4];"
                 : "=r"(r[0]), "=r"(r[1]), "=r"(r[2]), "=r"(r[3]) : "r"(addr));
}
__device__ __forceinline__ void mma16816(float* c, const uint32_t* a, const uint32_t* b) {
    asm volatile(
        "mma.sync.aligned.m16n8k16.row.col.f32.bf16.bf16.f32 "
        "{%0,%1,%2,%3},{%4,%5,%6,%7},{%8,%9},{%0,%1,%2,%3};"
        : "+f"(c[0]), "+f"(c[1]), "+f"(c[2]), "+f"(c[3])
        : "r"(a[0]), "r"(a[1]), "r"(a[2]), "r"(a[3]), "r"(b[0]), "r"(b[1]));
}
__device__ __forceinline__ void split2(float a, float b, uint32_t& hi, uint32_t& lo) {
    __nv_bfloat16 ha = __float2bfloat16(a), hb = __float2bfloat16(b);
    float la = a - __bfloat162float(ha);
    float lb = b - __bfloat162float(hb);
    __nv_bfloat162 H = __halves2bfloat162(ha, hb);
    __nv_bfloat162 L = __floats2bfloat162_rn(la, lb);
    hi = reinterpret_cast<uint32_t&>(H);
    lo = reinterpret_cast<uint32_t&>(L);
}

// SMEM tile geometry: rows of 32 bf16 (64B) padded to 80B (conflict-free ldmatrix)
#define ROWB 80
#define TSZ  (128 * ROWB)      // 10240 per tile (Ah/Al/Bh/Bl)
#define STAGEB (4 * TSZ)       // 40960 per stage
#define SMEM_GEMM (2 * STAGEB) // 81920

// ============================================================================
// Gate
// ============================================================================
__global__ void gate_kernel(const float* __restrict__ x,
                            const float* __restrict__ Wg,
                            const float* __restrict__ bg,
                            float* __restrict__ gates_out) {
    __shared__ float sWg[DD * NE];
    for (int i = threadIdx.x; i < DD * NE; i += blockDim.x) sWg[i] = Wg[i];
    __syncthreads();

    const int warp = threadIdx.x >> 5;
    const int lane = threadIdx.x & 31;
    const int t = blockIdx.x * (blockDim.x >> 5) + warp;
    if (t >= NTOK) return;

    float acc[NE];
#pragma unroll
    for (int e = 0; e < NE; e++) acc[e] = 0.f;
    const float* xr = x + (size_t)t * DD;
    for (int d = lane; d < DD; d += 32) {
        float xv = xr[d];
#pragma unroll
        for (int e = 0; e < NE; e++) acc[e] = fmaf(xv, sWg[d * NE + e], acc[e]);
    }
#pragma unroll
    for (int off = 16; off; off >>= 1)
#pragma unroll
        for (int e = 0; e < NE; e++) acc[e] += __shfl_xor_sync(0xffffffffu, acc[e], off);

    if (lane == 0) {
        float lg[NE];
        float m = -1e30f;
#pragma unroll
        for (int e = 0; e < NE; e++) { lg[e] = acc[e] + bg[e]; m = fmaxf(m, lg[e]); }
        float s = 0.f;
#pragma unroll
        for (int e = 0; e < NE; e++) { lg[e] = expf(lg[e] - m); s += lg[e]; }
        float inv = 1.f / s;
#pragma unroll
        for (int e = 0; e < NE; e++) lg[e] *= inv;
#pragma unroll
        for (int e = 0; e < NE; e++) gates_out[(size_t)t * NE + e] = lg[e];

        int i1 = 0; float v1 = lg[0];
#pragma unroll
        for (int e = 1; e < NE; e++) if (lg[e] > v1) { v1 = lg[e]; i1 = e; }
        int i2 = -1; float v2 = -1.f;
#pragma unroll
        for (int e = 0; e < NE; e++) if (e != i1 && lg[e] > v2) { v2 = lg[e]; i2 = e; }

        int p1 = atomicAdd(&g_cnt[i1], 1);
        g_tok[i1 * CAP + p1] = t; g_w[i1 * CAP + p1] = v1;
        int p2 = atomicAdd(&g_cnt[i2], 1);
        g_tok[i2 * CAP + p2] = t; g_w[i2 * CAP + p2] = v2;
        g_slot[2 * t + 0] = i1 * CAP + p1;
        g_slot[2 * t + 1] = i2 * CAP + p2;
    }
}

// ============================================================================
// x split: fp32 -> bf16 hi/lo
// ============================================================================
__global__ void xsplit_kernel(const float* __restrict__ x) {
    const int i = blockIdx.x * blockDim.x + threadIdx.x;   // over NTOK*DD/4
    float4 v = ((const float4*)x)[i];
    uint32_t h0, l0, h1, l1;
    split2(v.x, v.y, h0, l0);
    split2(v.z, v.w, h1, l1);
    *(uint2*)(g_x_hi + (size_t)i * 4) = make_uint2(h0, h1);
    *(uint2*)(g_x_lo + (size_t)i * 4) = make_uint2(l0, l1);
}

// ============================================================================
// Weight transpose + split: W [e][K][N] fp32 -> [e][N][K] bf16 hi/lo
// ============================================================================
__global__ void wsplit_kernel(const float* __restrict__ W, int which, int K, int N) {
    __shared__ float t[32][33];
    const int e = blockIdx.z;
    const int n0 = blockIdx.x * 32, k0 = blockIdx.y * 32;
    const int tx = threadIdx.x, ty = threadIdx.y;
    const float* We = W + (size_t)e * K * N;
#pragma unroll
    for (int j = 0; j < 32; j += 8)
        t[ty + j][tx] = We[(size_t)(k0 + ty + j) * N + n0 + tx];
    __syncthreads();
    __nv_bfloat16* hi = (which ? g_w2t_hi : g_w1t_hi) + (size_t)e * K * N;
    __nv_bfloat16* lo = (which ? g_w2t_lo : g_w1t_lo) + (size_t)e * K * N;
#pragma unroll
    for (int j = 0; j < 32; j += 8) {
        float v = t[tx][ty + j];
        __nv_bfloat16 h = __float2bfloat16(v);
        float rem = v - __bfloat162float(h);
        size_t o = (size_t)(n0 + ty + j) * K + k0 + tx;
        hi[o] = h;
        lo[o] = __float2bfloat16(rem);
    }
}

// ============================================================================
// Expert GEMM: C = A @ B^T (+bias, epilogue), bf16 3-term split via mma.sync
//   IS_FC1: A = gathered g_x (K=512),  B = w1t (N=2048), epi = relu->split->g_h
//   else :  A = g_h slots   (K=2048),  B = w2t (N=512),  epi = w*(y+b)->g_y
// CTA 128x128, 8 warps (warp 32x64), cp.async double buffer
// ============================================================================
template<int KDIM, bool IS_FC1>
__global__ void __launch_bounds__(256, 1)
moe_gemm(const float* __restrict__ bias_g) {
    extern __shared__ __align__(16) char smem[];
    const uint32_t sb = smem_u32(smem);
    const int e = blockIdx.z;
    const int cnt = g_cnt[e];
    const int m0 = blockIdx.x * 128;
    if (m0 >= cnt) return;
    const int n0 = blockIdx.y * 128;
    const int NN = IS_FC1 ? HH : DD;

    const int tid = threadIdx.x;
    const int lane = tid & 31;
    const int wid = tid >> 5;
    const int mbase = (wid >> 1) * 32;   // 4 warps in M
    const int nbase = (wid & 1) * 64;    // 2 warps in N

    __shared__ int   rows[128];
    __shared__ float sbias[128];
    if (tid < 128) {
        int r = m0 + tid; if (r >= cnt) r = cnt - 1;
        rows[tid] = IS_FC1 ? g_tok[e * CAP + r] : (e * CAP + r);
        sbias[tid] = bias_g[(size_t)e * NN + n0 + tid];
    }
    __syncthreads();

    const __nv_bfloat16* Ah_g = IS_FC1 ? g_x_hi : g_h_hi;
    const __nv_bfloat16* Al_g = IS_FC1 ? g_x_lo : g_h_lo;
    const __nv_bfloat16* Bh_g = (IS_FC1 ? g_w1t_hi : g_w2t_hi) + (size_t)e * NN * KDIM;
    const __nv_bfloat16* Bl_g = (IS_FC1 ? g_w1t_lo : g_w2t_lo) + (size_t)e * NN * KDIM;

    auto load_stage = [&](int s, int buf) {
        const int k0 = s * 32;
        const uint32_t sa = sb + buf * STAGEB;
#pragma unroll
        for (int it = 0; it < 2; it++) {
            int i = tid + it * 256;
            int r = i >> 2, c = i & 3;
            uint32_t d = sa + r * ROWB + c * 16;
            size_t asrc = (size_t)rows[r] * KDIM + k0 + c * 8;
            CP_ASYNC16(d,           Ah_g + asrc);
            CP_ASYNC16(d + TSZ,     Al_g + asrc);
            size_t bsrc = (size_t)(n0 + r) * KDIM + k0 + c * 8;
            CP_ASYNC16(d + 2 * TSZ, Bh_g + bsrc);
            CP_ASYNC16(d + 3 * TSZ, Bl_g + bsrc);
        }
        CP_COMMIT();
    };

    float c[2][8][4];
#pragma unroll
    for (int im = 0; im < 2; im++)
#pragma unroll
        for (int jn = 0; jn < 8; jn++)
#pragma unroll
            for (int q = 0; q < 4; q++) c[im][jn][q] = 0.f;

    constexpr int S = KDIM / 32;
    load_stage(0, 0);

    for (int s = 0; s < S; s++) {
        if (s + 1 < S) { load_stage(s + 1, (s + 1) & 1); CP_WAIT(1); }
        else           { CP_WAIT(0); }
        __syncthreads();

        const uint32_t base = sb + (s & 1) * STAGEB;
#pragma unroll
        for (int ks = 0; ks < 2; ks++) {
            uint32_t ah[2][4], al[2][4], bh[8][2], bl[8][2];
#pragma unroll
            for (int im = 0; im < 2; im++) {
                uint32_t row = mbase + im * 16 + (lane & 7) + ((lane >> 3) & 1) * 8;
                uint32_t addr = base + row * ROWB + (ks * 16 + (lane >> 4) * 8) * 2;
                ldsm4(ah[im], addr);
                ldsm4(al[im], addr + TSZ);
            }
#pragma unroll
            for (int jn = 0; jn < 4; jn++) {
                uint32_t rowb = nbase + jn * 16 + (lane & 7) + (lane >> 4) * 8;
                uint32_t addr = base + 2 * TSZ + rowb * ROWB + (ks * 16 + ((lane >> 3) & 1) * 8) * 2;
                uint32_t t[4];
                ldsm4(t, addr);
                bh[jn * 2][0] = t[0]; bh[jn * 2][1] = t[1];
                bh[jn * 2 + 1][0] = t[2]; bh[jn * 2 + 1][1] = t[3];
                ldsm4(t, addr + TSZ);
                bl[jn * 2][0] = t[0]; bl[jn * 2][1] = t[1];
                bl[jn * 2 + 1][0] = t[2]; bl[jn * 2 + 1][1] = t[3];
            }
#pragma unroll
            for (int im = 0; im < 2; im++)
#pragma unroll
                for (int jn = 0; jn < 8; jn++) {
                    mma16816(c[im][jn], ah[im], bh[jn]);
                    mma16816(c[im][jn], ah[im], bl[jn]);
                    mma16816(c[im][jn], al[im], bh[jn]);
                }
        }
        __syncthreads();
    }

    // ---- epilogue ----
#pragma unroll
    for (int im = 0; im < 2; im++) {
        const int rloc0 = mbase + im * 16 + (lane >> 2);
#pragma unroll
        for (int p = 0; p < 2; p++) {
            const int grow = m0 + rloc0 + p * 8;
            if (grow >= cnt) continue;
            if (IS_FC1) {
                size_t hb = ((size_t)e * CAP + grow) * HH;
#pragma unroll
                for (int jn = 0; jn < 8; jn++) {
                    int cc = nbase + jn * 8 + (lane & 3) * 2;
                    float v0 = fmaxf(c[im][jn][2 * p]     + sbias[cc],     0.f);
                    float v1 = fmaxf(c[im][jn][2 * p + 1] + sbias[cc + 1], 0.f);
                    uint32_t hi, lo;
                    split2(v0, v1, hi, lo);
                    *(uint32_t*)(g_h_hi + hb + n0 + cc) = hi;
                    *(uint32_t*)(g_h_lo + hb + n0 + cc) = lo;
                }
            } else {
                float wv = g_w[e * CAP + grow];
                size_t yb = ((size_t)e * CAP + grow) * DD;
#pragma unroll
                for (int jn = 0; jn < 8; jn++) {
                    int cc = nbase + jn * 8 + (lane & 3) * 2;
                    float2 v;
                    v.x = (c[im][jn][2 * p]     + sbias[cc])     * wv;
                    v.y = (c[im][jn][2 * p + 1] + sbias[cc + 1]) * wv;
                    *(float2*)(g_y + yb + n0 + cc) = v;
                }
            }
        }
    }
}

// ============================================================================
// Combine: out[t] = g_y[slot0] + g_y[slot1]
// ============================================================================
__global__ void combine_kernel(float* __restrict__ out) {
    const int t = blockIdx.x;
    const int q = threadIdx.x;  // 128 threads, float4 each
    const int s0 = g_slot[2 * t], s1 = g_slot[2 * t + 1];
    const float4* y0 = (const float4*)(g_y + (size_t)s0 * DD);
    const float4* y1 = (const float4*)(g_y + (size_t)s1 * DD);
    float4 a = y0[q], b = y1[q];
    ((float4*)(out + (size_t)t * DD))[q] =
        make_float4(a.x + b.x, a.y + b.y, a.z + b.z, a.w + b.w);
}

// ============================================================================
// launch
// ============================================================================
extern "C" void kernel_launch(void* const* d_in, const int* in_sizes, int n_in,
                              void* d_out, int out_size) {
    const float* x  = (const float*)d_in[0];
    const float* Wg = (const float*)d_in[1];
    const float* bg = (const float*)d_in[2];
    const float* W1 = (const float*)d_in[3];
    const float* b1 = (const float*)d_in[4];
    const float* W2 = (const float*)d_in[5];
    const float* b2 = (const float*)d_in[6];
    float* out = (float*)d_out;

    void* cntp = nullptr;
    cudaGetSymbolAddress(&cntp, g_cnt);
    cudaMemsetAsync(cntp, 0, NE * sizeof(int));

    float* gates_out = out + (size_t)NTOK * DD;

    cudaFuncSetAttribute(moe_gemm<DD, true>,  cudaFuncAttributeMaxDynamicSharedMemorySize, SMEM_GEMM);
    cudaFuncSetAttribute(moe_gemm<HH, false>, cudaFuncAttributeMaxDynamicSharedMemorySize, SMEM_GEMM);

    gate_kernel<<<NTOK / 8, 256>>>(x, Wg, bg, gates_out);
    xsplit_kernel<<<NTOK * DD / 4 / 256, 256>>>(x);
    wsplit_kernel<<<dim3(HH / 32, DD / 32, NE), dim3(32, 8)>>>(W1, 0, DD, HH);
    wsplit_kernel<<<dim3(DD / 32, HH / 32, NE), dim3(32, 8)>>>(W2, 1, HH, DD);

    moe_gemm<DD, true ><<<dim3(CAP / 128, HH / 128, NE), 256, SMEM_GEMM>>>(b1);
    moe_gemm<HH, false><<<dim3(CAP / 128, DD / 128, NE), 256, SMEM_GEMM>>>(b2);

    combine_kernel<<<NTOK, 128>>>(out);
}

// round 4
// speedup vs baseline: 2.2319x; 1.0323x over previous
#include <cuda_runtime.h>
#include <cuda_bf16.h>
#include <cstdint>

#define NE 8
#define DD 512
#define HH 2048
#define NTOK 4096
#define CAP 4096

// ---------------- device scratch (static, allocation-free) ----------------
__device__ int   g_cnt[NE];
__device__ int   g_tok[NE * CAP];
__device__ float g_w[NE * CAP];
__device__ __nv_bfloat16 g_x_hi[(size_t)NTOK * DD];
__device__ __nv_bfloat16 g_x_lo[(size_t)NTOK * DD];
__device__ __nv_bfloat16 g_h_hi[(size_t)NE * CAP * HH];
__device__ __nv_bfloat16 g_h_lo[(size_t)NE * CAP * HH];
__device__ __nv_bfloat16 g_w1t_hi[(size_t)NE * HH * DD];   // [e][n(H)][k(D)]
__device__ __nv_bfloat16 g_w1t_lo[(size_t)NE * HH * DD];
__device__ __nv_bfloat16 g_w2t_hi[(size_t)NE * DD * HH];   // [e][n(D)][k(H)]
__device__ __nv_bfloat16 g_w2t_lo[(size_t)NE * DD * HH];

// ---------------- helpers ----------------
__device__ __forceinline__ uint32_t smem_u32(const void* p) {
    uint32_t a;
    asm("{ .reg .u64 t; cvta.to.shared.u64 t, %1; cvt.u32.u64 %0, t; }" : "=r"(a) : "l"(p));
    return a;
}
#define CP_ASYNC16(dst, src) \
    asm volatile("cp.async.cg.shared.global [%0], [%1], 16;" :: "r"(dst), "l"(src) : "memory")
#define CP_COMMIT() asm volatile("cp.async.commit_group;" ::: "memory")
#define CP_WAIT(n)  asm volatile("cp.async.wait_group %0;" :: "n"(n) : "memory")

__device__ __forceinline__ void ldsm4(uint32_t* r, uint32_t addr) {
    asm volatile("ldmatrix.sync.aligned.m8n8.x4.shared.b16 {%0,%1,%2,%3}, [%4];"
                 : "=r"(r[0]), "=r"(r[1]), "=r"(r[2]), "=r"(r[3]) : "r"(addr));
}
__device__ __forceinline__ void mma16816(float* c, const uint32_t* a, const uint32_t* b) {
    asm volatile(
        "mma.sync.aligned.m16n8k16.row.col.f32.bf16.bf16.f32 "
        "{%0,%1,%2,%3},{%4,%5,%6,%7},{%8,%9},{%0,%1,%2,%3};"
        : "+f"(c[0]), "+f"(c[1]), "+f"(c[2]), "+f"(c[3])
        : "r"(a[0]), "r"(a[1]), "r"(a[2]), "r"(a[3]), "r"(b[0]), "r"(b[1]));
}
__device__ __forceinline__ void split2(float a, float b, uint32_t& hi, uint32_t& lo) {
    __nv_bfloat16 ha = __float2bfloat16(a), hb = __float2bfloat16(b);
    float la = a - __bfloat162float(ha);
    float lb = b - __bfloat162float(hb);
    __nv_bfloat162 H = __halves2bfloat162(ha, hb);
    __nv_bfloat162 L = __floats2bfloat162_rn(la, lb);
    hi = reinterpret_cast<uint32_t&>(H);
    lo = reinterpret_cast<uint32_t&>(L);
}

// SMEM tile geometry: rows of 32 bf16 (64B) padded to 80B (conflict-free ldmatrix)
#define ROWB 80
#define TSZ  (128 * ROWB)      // 10240 per tile (Ah/Al/Bh/Bl)
#define STAGEB (4 * TSZ)       // 40960 per stage
#define NST 5
#define SMEM_GEMM (NST * STAGEB)  // 204800

// ============================================================================
// Gate
// ============================================================================
__global__ void gate_kernel(const float* __restrict__ x,
                            const float* __restrict__ Wg,
                            const float* __restrict__ bg,
                            float* __restrict__ gates_out) {
    __shared__ float sWg[DD * NE];
    for (int i = threadIdx.x; i < DD * NE; i += blockDim.x) sWg[i] = Wg[i];
    __syncthreads();

    const int warp = threadIdx.x >> 5;
    const int lane = threadIdx.x & 31;
    const int t = blockIdx.x * (blockDim.x >> 5) + warp;
    if (t >= NTOK) return;

    float acc[NE];
#pragma unroll
    for (int e = 0; e < NE; e++) acc[e] = 0.f;
    const float* xr = x + (size_t)t * DD;
    for (int d = lane; d < DD; d += 32) {
        float xv = xr[d];
#pragma unroll
        for (int e = 0; e < NE; e++) acc[e] = fmaf(xv, sWg[d * NE + e], acc[e]);
    }
#pragma unroll
    for (int off = 16; off; off >>= 1)
#pragma unroll
        for (int e = 0; e < NE; e++) acc[e] += __shfl_xor_sync(0xffffffffu, acc[e], off);

    if (lane == 0) {
        float lg[NE];
        float m = -1e30f;
#pragma unroll
        for (int e = 0; e < NE; e++) { lg[e] = acc[e] + bg[e]; m = fmaxf(m, lg[e]); }
        float s = 0.f;
#pragma unroll
        for (int e = 0; e < NE; e++) { lg[e] = expf(lg[e] - m); s += lg[e]; }
        float inv = 1.f / s;
#pragma unroll
        for (int e = 0; e < NE; e++) lg[e] *= inv;
#pragma unroll
        for (int e = 0; e < NE; e++) gates_out[(size_t)t * NE + e] = lg[e];

        int i1 = 0; float v1 = lg[0];
#pragma unroll
        for (int e = 1; e < NE; e++) if (lg[e] > v1) { v1 = lg[e]; i1 = e; }
        int i2 = -1; float v2 = -1.f;
#pragma unroll
        for (int e = 0; e < NE; e++) if (e != i1 && lg[e] > v2) { v2 = lg[e]; i2 = e; }

        int p1 = atomicAdd(&g_cnt[i1], 1);
        g_tok[i1 * CAP + p1] = t; g_w[i1 * CAP + p1] = v1;
        int p2 = atomicAdd(&g_cnt[i2], 1);
        g_tok[i2 * CAP + p2] = t; g_w[i2 * CAP + p2] = v2;
    }
}

// ============================================================================
// x split: fp32 -> bf16 hi/lo
// ============================================================================
__global__ void xsplit_kernel(const float* __restrict__ x) {
    const int i = blockIdx.x * blockDim.x + threadIdx.x;
    float4 v = ((const float4*)x)[i];
    uint32_t h0, l0, h1, l1;
    split2(v.x, v.y, h0, l0);
    split2(v.z, v.w, h1, l1);
    *(uint2*)(g_x_hi + (size_t)i * 4) = make_uint2(h0, h1);
    *(uint2*)(g_x_lo + (size_t)i * 4) = make_uint2(l0, l1);
}

// ============================================================================
// Weight transpose + split: W [e][K][N] fp32 -> [e][N][K] bf16 hi/lo
// ============================================================================
__global__ void wsplit_kernel(const float* __restrict__ W, int which, int K, int N) {
    __shared__ float t[32][33];
    const int e = blockIdx.z;
    const int n0 = blockIdx.x * 32, k0 = blockIdx.y * 32;
    const int tx = threadIdx.x, ty = threadIdx.y;
    const float* We = W + (size_t)e * K * N;
#pragma unroll
    for (int j = 0; j < 32; j += 8)
        t[ty + j][tx] = We[(size_t)(k0 + ty + j) * N + n0 + tx];
    __syncthreads();
    __nv_bfloat16* hi = (which ? g_w2t_hi : g_w1t_hi) + (size_t)e * K * N;
    __nv_bfloat16* lo = (which ? g_w2t_lo : g_w1t_lo) + (size_t)e * K * N;
#pragma unroll
    for (int j = 0; j < 32; j += 8) {
        float v = t[tx][ty + j];
        __nv_bfloat16 h = __float2bfloat16(v);
        float rem = v - __bfloat162float(h);
        size_t o = (size_t)(n0 + ty + j) * K + k0 + tx;
        hi[o] = h;
        lo[o] = __float2bfloat16(rem);
    }
}

// ============================================================================
// Expert GEMM: C = A @ B^T (+bias, epilogue), bf16 3-term split via mma.sync
//   IS_FC1: A = gathered g_x (K=512),  B = w1t (N=2048), epi = relu->split->g_h
//   else :  A = g_h slots   (K=2048),  B = w2t (N=512),  epi = atomicAdd out
// CTA 128x128, 8 warps (warp 32x64), 5-stage cp.async pipeline, 1 sync/iter
// ============================================================================
template<int KDIM, bool IS_FC1>
__global__ void __launch_bounds__(256, 1)
moe_gemm(const float* __restrict__ bias_g, float* __restrict__ out) {
    extern __shared__ __align__(16) char smem[];
    const uint32_t sb = smem_u32(smem);
    const int e = blockIdx.z;
    const int cnt = g_cnt[e];
    const int m0 = blockIdx.x * 128;
    if (m0 >= cnt) return;
    const int n0 = blockIdx.y * 128;
    const int NN = IS_FC1 ? HH : DD;

    const int tid = threadIdx.x;
    const int lane = tid & 31;
    const int wid = tid >> 5;
    const int mbase = (wid >> 1) * 32;   // 4 warps in M
    const int nbase = (wid & 1) * 64;    // 2 warps in N

    __shared__ int   rows[128];
    __shared__ float sbias[128];
    if (tid < 128) {
        int r = m0 + tid; if (r >= cnt) r = cnt - 1;
        rows[tid] = IS_FC1 ? g_tok[e * CAP + r] : (e * CAP + r);
        sbias[tid] = bias_g[(size_t)e * NN + n0 + tid];
    }
    __syncthreads();

    const __nv_bfloat16* Ah_g = IS_FC1 ? g_x_hi : g_h_hi;
    const __nv_bfloat16* Al_g = IS_FC1 ? g_x_lo : g_h_lo;
    const __nv_bfloat16* Bh_g = (IS_FC1 ? g_w1t_hi : g_w2t_hi) + (size_t)e * NN * KDIM;
    const __nv_bfloat16* Bl_g = (IS_FC1 ? g_w1t_lo : g_w2t_lo) + (size_t)e * NN * KDIM;

    // per-thread fixed load coords: thread handles rows r1=tid>>2 (+64), col c=tid&3
    const int lr = tid >> 2, lc = tid & 3;
    auto load_stage = [&](int s, int buf) {
        const int k0 = s * 32;
        const uint32_t sa = sb + buf * STAGEB;
#pragma unroll
        for (int it = 0; it < 2; it++) {
            int r = lr + it * 64;
            uint32_t d = sa + r * ROWB + lc * 16;
            size_t asrc = (size_t)rows[r] * KDIM + k0 + lc * 8;
            CP_ASYNC16(d,           Ah_g + asrc);
            CP_ASYNC16(d + TSZ,     Al_g + asrc);
            size_t bsrc = (size_t)(n0 + r) * KDIM + k0 + lc * 8;
            CP_ASYNC16(d + 2 * TSZ, Bh_g + bsrc);
            CP_ASYNC16(d + 3 * TSZ, Bl_g + bsrc);
        }
        CP_COMMIT();
    };

    float c[2][8][4];
#pragma unroll
    for (int im = 0; im < 2; im++)
#pragma unroll
        for (int jn = 0; jn < 8; jn++)
#pragma unroll
            for (int q = 0; q < 4; q++) c[im][jn][q] = 0.f;

    constexpr int S = KDIM / 32;
    // prologue: fill NST-1 stages (one commit group each)
#pragma unroll
    for (int p = 0; p < NST - 1; p++) {
        if (p < S) load_stage(p, p);
        else       CP_COMMIT();
    }

    int buf = 0;
    for (int s = 0; s < S; s++) {
        CP_WAIT(NST - 2);        // stage s resident
        __syncthreads();         // data ready + previous buf consumers done
        // issue stage s+NST-1 into buf (s-1)%NST (freed by last iter's compute)
        {
            int sn = s + NST - 1;
            if (sn < S) load_stage(sn, sn % NST);
            else        CP_COMMIT();   // keep group count in lockstep
        }
        const uint32_t base = sb + buf * STAGEB;
#pragma unroll
        for (int ks = 0; ks < 2; ks++) {
            uint32_t ah[2][4], al[2][4], bh[8][2], bl[8][2];
#pragma unroll
            for (int im = 0; im < 2; im++) {
                uint32_t row = mbase + im * 16 + (lane & 7) + ((lane >> 3) & 1) * 8;
                uint32_t addr = base + row * ROWB + (ks * 16 + (lane >> 4) * 8) * 2;
                ldsm4(ah[im], addr);
                ldsm4(al[im], addr + TSZ);
            }
#pragma unroll
            for (int jn = 0; jn < 4; jn++) {
                uint32_t rowb = nbase + jn * 16 + (lane & 7) + (lane >> 4) * 8;
                uint32_t addr = base + 2 * TSZ + rowb * ROWB + (ks * 16 + ((lane >> 3) & 1) * 8) * 2;
                uint32_t t[4];
                ldsm4(t, addr);
                bh[jn * 2][0] = t[0]; bh[jn * 2][1] = t[1];
                bh[jn * 2 + 1][0] = t[2]; bh[jn * 2 + 1][1] = t[3];
                ldsm4(t, addr + TSZ);
                bl[jn * 2][0] = t[0]; bl[jn * 2][1] = t[1];
                bl[jn * 2 + 1][0] = t[2]; bl[jn * 2 + 1][1] = t[3];
            }
#pragma unroll
            for (int im = 0; im < 2; im++)
#pragma unroll
                for (int jn = 0; jn < 8; jn++) {
                    mma16816(c[im][jn], ah[im], bh[jn]);
                    mma16816(c[im][jn], ah[im], bl[jn]);
                    mma16816(c[im][jn], al[im], bh[jn]);
                }
        }
        buf++; if (buf == NST) buf = 0;
    }

    // ---- epilogue ----
#pragma unroll
    for (int im = 0; im < 2; im++) {
        const int rloc0 = mbase + im * 16 + (lane >> 2);
#pragma unroll
        for (int p = 0; p < 2; p++) {
            const int grow = m0 + rloc0 + p * 8;
            if (grow >= cnt) continue;
            if (IS_FC1) {
                size_t hb = ((size_t)e * CAP + grow) * HH;
#pragma unroll
                for (int jn = 0; jn < 8; jn++) {
                    int cc = nbase + jn * 8 + (lane & 3) * 2;
                    float v0 = fmaxf(c[im][jn][2 * p]     + sbias[cc],     0.f);
                    float v1 = fmaxf(c[im][jn][2 * p + 1] + sbias[cc + 1], 0.f);
                    uint32_t hi, lo;
                    split2(v0, v1, hi, lo);
                    *(uint32_t*)(g_h_hi + hb + n0 + cc) = hi;
                    *(uint32_t*)(g_h_lo + hb + n0 + cc) = lo;
                }
            } else {
                float wv = g_w[e * CAP + grow];
                int tok = g_tok[e * CAP + grow];
                float* orow = out + (size_t)tok * DD + n0;
#pragma unroll
                for (int jn = 0; jn < 8; jn++) {
                    int cc = nbase + jn * 8 + (lane & 3) * 2;
                    atomicAdd(&orow[cc],     (c[im][jn][2 * p]     + sbias[cc])     * wv);
                    atomicAdd(&orow[cc + 1], (c[im][jn][2 * p + 1] + sbias[cc + 1]) * wv);
                }
            }
        }
    }
}

// ============================================================================
// launch
// ============================================================================
extern "C" void kernel_launch(void* const* d_in, const int* in_sizes, int n_in,
                              void* d_out, int out_size) {
    const float* x  = (const float*)d_in[0];
    const float* Wg = (const float*)d_in[1];
    const float* bg = (const float*)d_in[2];
    const float* W1 = (const float*)d_in[3];
    const float* b1 = (const float*)d_in[4];
    const float* W2 = (const float*)d_in[5];
    const float* b2 = (const float*)d_in[6];
    float* out = (float*)d_out;

    void* cntp = nullptr;
    cudaGetSymbolAddress(&cntp, g_cnt);
    cudaMemsetAsync(cntp, 0, NE * sizeof(int));
    cudaMemsetAsync(out, 0, (size_t)NTOK * DD * sizeof(float));

    float* gates_out = out + (size_t)NTOK * DD;

    cudaFuncSetAttribute(moe_gemm<DD, true>,  cudaFuncAttributeMaxDynamicSharedMemorySize, SMEM_GEMM);
    cudaFuncSetAttribute(moe_gemm<HH, false>, cudaFuncAttributeMaxDynamicSharedMemorySize, SMEM_GEMM);

    gate_kernel<<<NTOK / 8, 256>>>(x, Wg, bg, gates_out);
    xsplit_kernel<<<NTOK * DD / 4 / 256, 256>>>(x);
    wsplit_kernel<<<dim3(HH / 32, DD / 32, NE), dim3(32, 8)>>>(W1, 0, DD, HH);
    wsplit_kernel<<<dim3(DD / 32, HH / 32, NE), dim3(32, 8)>>>(W2, 1, HH, DD);

    moe_gemm<DD, true ><<<dim3(CAP / 128, HH / 128, NE), 256, SMEM_GEMM>>>(b1, nullptr);
    moe_gemm<HH, false><<<dim3(CAP / 128, DD / 128, NE), 256, SMEM_GEMM>>>(b2, out);
}